// round 2
// baseline (speedup 1.0000x reference)
#include <cuda_runtime.h>
#include <math.h>

// FFF: fast-feedforward conditional tree MLP.
// B=8192 samples, D_in = D_out = 2048, depth 11 -> 12 routing steps, 4095 nodes.
//
// Strategy:
//  k1: transpose W_out (2048 x 4095) -> g_WoutT (4095 x 2048) so output columns
//      become contiguous rows (coalesced float4 loads).
//  k2: one 128-thread block per sample. x row cached in registers (4 float4 each).
//      12 sequential steps: load W_in[node] row + W_outT[node] row (both issued
//      up front so the W_out latency hides under the reduction barrier),
//      block-reduce the dot in a FIXED order (deterministic fp32 signs),
//      exact GELU, accumulate output in registers, descend the tree.

#define DEPTH    11
#define NSTEPS   (DEPTH + 1)
#define N_NODES  4095
#define DDIM     2048
#define D4       (DDIM / 4)     // 512 float4 per row
#define BATCH    8192
#define THREADS  128

// Transposed W_out scratch (allocation-free __device__ global).
__device__ float g_WoutT[(size_t)N_NODES * DDIM];

__global__ void transpose_wout(const float* __restrict__ Wout) {
    __shared__ float tile[32][33];
    int n0 = blockIdx.x * 32;   // node dim (4095)
    int o0 = blockIdx.y * 32;   // output dim (2048)
    int n = n0 + threadIdx.x;
    int o = o0 + threadIdx.y;
    if (o < DDIM && n < N_NODES)
        tile[threadIdx.y][threadIdx.x] = Wout[(size_t)o * N_NODES + n];
    __syncthreads();
    int n2 = n0 + threadIdx.y;
    int o2 = o0 + threadIdx.x;
    if (n2 < N_NODES && o2 < DDIM)
        g_WoutT[(size_t)n2 * DDIM + o2] = tile[threadIdx.x][threadIdx.y];
}

__device__ __forceinline__ float dot4(float4 a, float4 b) {
    return fmaf(a.x, b.x, fmaf(a.y, b.y, fmaf(a.z, b.z, a.w * b.w)));
}

__device__ __forceinline__ void fma4(float4& a, float g, float4 v) {
    a.x = fmaf(g, v.x, a.x);
    a.y = fmaf(g, v.y, a.y);
    a.z = fmaf(g, v.z, a.z);
    a.w = fmaf(g, v.w, a.w);
}

__global__ __launch_bounds__(THREADS) void fff_kernel(
    const float* __restrict__ x,
    const float* __restrict__ Win,
    float*       __restrict__ out)
{
    const int b    = blockIdx.x;
    const int tid  = threadIdx.x;
    const int lane = tid & 31;
    const int warp = tid >> 5;

    const float4* __restrict__ x4   = reinterpret_cast<const float4*>(x) + (size_t)b * D4;
    const float4* __restrict__ Win4 = reinterpret_cast<const float4*>(Win);
    const float4* __restrict__ Wt4  = reinterpret_cast<const float4*>(g_WoutT);

    // Cache this sample's x row in registers (coalesced LDG.128).
    float4 xr0 = x4[tid];
    float4 xr1 = x4[tid + 128];
    float4 xr2 = x4[tid + 256];
    float4 xr3 = x4[tid + 384];

    float4 a0 = make_float4(0.f, 0.f, 0.f, 0.f);
    float4 a1 = make_float4(0.f, 0.f, 0.f, 0.f);
    float4 a2 = make_float4(0.f, 0.f, 0.f, 0.f);
    float4 a3 = make_float4(0.f, 0.f, 0.f, 0.f);

    __shared__ float red[2][4];

    int node = 0;
    #pragma unroll
    for (int d = 0; d < NSTEPS; ++d) {
        const float4* __restrict__ wr = Win4 + (size_t)node * D4;
        const float4* __restrict__ vr = Wt4  + (size_t)node * D4;

        // Issue all 8 wide loads up front; W_outT latency hides under reduction.
        float4 w0 = wr[tid];
        float4 w1 = wr[tid + 128];
        float4 w2 = wr[tid + 256];
        float4 w3 = wr[tid + 384];
        float4 v0 = vr[tid];
        float4 v1 = vr[tid + 128];
        float4 v2 = vr[tid + 256];
        float4 v3 = vr[tid + 384];

        float p = dot4(w0, xr0);
        p += dot4(w1, xr1);
        p += dot4(w2, xr2);
        p += dot4(w3, xr3);

        // Warp reduce (fixed order -> deterministic).
        #pragma unroll
        for (int off = 16; off > 0; off >>= 1)
            p += __shfl_down_sync(0xffffffffu, p, off);

        if (lane == 0) red[d & 1][warp] = p;
        __syncthreads();

        // Every thread recomputes the same fixed-order sum -> identical score.
        float score = (red[d & 1][0] + red[d & 1][1]) + (red[d & 1][2] + red[d & 1][3]);

        // Exact GELU: 0.5*s*(1+erf(s/sqrt(2)))
        float g = 0.5f * score * (1.0f + erff(score * 0.70710678118654752f));

        fma4(a0, g, v0);
        fma4(a1, g, v1);
        fma4(a2, g, v2);
        fma4(a3, g, v3);

        node = node * 2 + 1 + (score >= 0.0f ? 1 : 0);
    }

    float4* __restrict__ o4 = reinterpret_cast<float4*>(out) + (size_t)b * D4;
    o4[tid]       = a0;
    o4[tid + 128] = a1;
    o4[tid + 256] = a2;
    o4[tid + 384] = a3;
}

extern "C" void kernel_launch(void* const* d_in, const int* in_sizes, int n_in,
                              void* d_out, int out_size)
{
    const float* x    = (const float*)d_in[0];   // (8192, 2048)
    const float* Win  = (const float*)d_in[1];   // (4095, 2048)
    const float* Wout = (const float*)d_in[2];   // (2048, 4095)
    float* out = (float*)d_out;                  // (8192, 2048)

    dim3 tb(32, 32);
    dim3 tg((N_NODES + 31) / 32, DDIM / 32);
    transpose_wout<<<tg, tb>>>(Wout);

    fff_kernel<<<BATCH, THREADS>>>(x, Win, out);
}

// round 4
// speedup vs baseline: 1.0826x; 1.0826x over previous
#include <cuda_runtime.h>
#include <math.h>

// FFF: fast-feedforward conditional tree MLP.
// B=8192, D_in=D_out=2048, depth 11 -> 12 routing steps, 4095 nodes.
//
// k1: transpose W_out (2048 x 4095) -> g_WoutT (4095 x 2048), 64x64 tiles,
//     fully coalesced both sides.
// k2: one 256-thread block per sample; 8 floats/thread of x/W_in/W_outT/acc
//     (low reg pressure -> 5 blocks/SM, ~62% occupancy). 12 sequential steps:
//     wide loads, per-warp shfl reduce, 8 partials summed in fixed tree order
//     (deterministic fp32 signs), exact GELU, register accumulation, descend.

#define DEPTH    11
#define NSTEPS   (DEPTH + 1)
#define N_NODES  4095
#define DDIM     2048
#define D4       (DDIM / 4)     // 512 float4 per row
#define BATCH    8192
#define THREADS  256

__device__ float g_WoutT[(size_t)N_NODES * DDIM];

// 64x64 tile transpose, 256 threads, 16 elems/thread, coalesced in and out.
__global__ __launch_bounds__(256) void transpose_wout(const float* __restrict__ Wout) {
    __shared__ float tile[64][65];
    const int n0 = blockIdx.x * 64;   // node dim (4095)
    const int o0 = blockIdx.y * 64;   // output dim (2048)
    const int tid = threadIdx.x;

    // Load: element e -> o_local = e/64, n_local = e%64. Coalesced in n.
    #pragma unroll
    for (int k = 0; k < 16; ++k) {
        int e = k * 256 + tid;
        int ol = e >> 6;
        int nl = e & 63;
        int n = n0 + nl;
        float v = 0.f;
        if (n < N_NODES)
            v = Wout[(size_t)(o0 + ol) * N_NODES + n];
        tile[nl][ol] = v;
    }
    __syncthreads();

    // Store: element e -> n_local = e/64, o_local = e%64. Coalesced in o.
    #pragma unroll
    for (int k = 0; k < 16; ++k) {
        int e = k * 256 + tid;
        int nl = e >> 6;
        int ol = e & 63;
        int n = n0 + nl;
        if (n < N_NODES)
            g_WoutT[(size_t)n * DDIM + (o0 + ol)] = tile[nl][ol];
    }
}

__device__ __forceinline__ float dot4(float4 a, float4 b) {
    return fmaf(a.x, b.x, fmaf(a.y, b.y, fmaf(a.z, b.z, a.w * b.w)));
}

__device__ __forceinline__ void fma4(float4& a, float g, float4 v) {
    a.x = fmaf(g, v.x, a.x);
    a.y = fmaf(g, v.y, a.y);
    a.z = fmaf(g, v.z, a.z);
    a.w = fmaf(g, v.w, a.w);
}

__global__ __launch_bounds__(THREADS) void fff_kernel(
    const float* __restrict__ x,
    const float* __restrict__ Win,
    float*       __restrict__ out)
{
    const int b    = blockIdx.x;
    const int tid  = threadIdx.x;
    const int lane = tid & 31;
    const int warp = tid >> 5;

    const float4* __restrict__ x4   = reinterpret_cast<const float4*>(x) + (size_t)b * D4;
    const float4* __restrict__ Win4 = reinterpret_cast<const float4*>(Win);
    const float4* __restrict__ Wt4  = reinterpret_cast<const float4*>(g_WoutT);

    // Cache this sample's x row in registers (coalesced LDG.128).
    float4 xr0 = x4[tid];
    float4 xr1 = x4[tid + 256];

    float4 a0 = make_float4(0.f, 0.f, 0.f, 0.f);
    float4 a1 = make_float4(0.f, 0.f, 0.f, 0.f);

    __shared__ float red[2][8];

    int node = 0;
    #pragma unroll
    for (int d = 0; d < NSTEPS; ++d) {
        const float4* __restrict__ wr = Win4 + (size_t)node * D4;
        const float4* __restrict__ vr = Wt4  + (size_t)node * D4;

        // Issue all wide loads up front; W_outT latency hides under reduction.
        float4 w0 = wr[tid];
        float4 w1 = wr[tid + 256];
        float4 v0 = vr[tid];
        float4 v1 = vr[tid + 256];

        float p = dot4(w0, xr0) + dot4(w1, xr1);

        // Warp reduce (fixed order -> deterministic).
        #pragma unroll
        for (int off = 16; off > 0; off >>= 1)
            p += __shfl_down_sync(0xffffffffu, p, off);

        if (lane == 0) red[d & 1][warp] = p;
        __syncthreads();

        // Every thread recomputes the same fixed-order tree sum -> identical score.
        const float* r = red[d & 1];
        float score = ((r[0] + r[1]) + (r[2] + r[3]))
                    + ((r[4] + r[5]) + (r[6] + r[7]));

        // Exact GELU: 0.5*s*(1+erf(s/sqrt(2)))
        float g = 0.5f * score * (1.0f + erff(score * 0.70710678118654752f));

        fma4(a0, g, v0);
        fma4(a1, g, v1);

        node = node * 2 + 1 + (score >= 0.0f ? 1 : 0);
    }

    float4* __restrict__ o4 = reinterpret_cast<float4*>(out) + (size_t)b * D4;
    o4[tid]       = a0;
    o4[tid + 256] = a1;
}

extern "C" void kernel_launch(void* const* d_in, const int* in_sizes, int n_in,
                              void* d_out, int out_size)
{
    const float* x    = (const float*)d_in[0];   // (8192, 2048)
    const float* Win  = (const float*)d_in[1];   // (4095, 2048)
    const float* Wout = (const float*)d_in[2];   // (2048, 4095)
    float* out = (float*)d_out;                  // (8192, 2048)

    dim3 tg((N_NODES + 63) / 64, DDIM / 64);     // 64 x 32 tiles
    transpose_wout<<<tg, 256>>>(Wout);

    fff_kernel<<<BATCH, THREADS>>>(x, Win, out);
}

// round 5
// speedup vs baseline: 1.2263x; 1.1328x over previous
#include <cuda_runtime.h>
#include <math.h>

// FFF: fast-feedforward conditional tree MLP.
// B=8192, D_in=D_out=2048, depth 11 -> 12 routing steps, 4095 nodes.
//
// k1: transpose W_out (2048 x 4095) -> g_WoutT (4095 x 2048), 64x64 tiles.
// k2: 128 threads per block, one sample per block (one serial routing chain
//     per block; maximize chains/SM). Per thread: 4 float4 of x (regs),
//     4 float4 acc (regs). Per step: 4-float4 W_in row load feeds the dot,
//     fixed-order reduce (deterministic), exact GELU; the W_outT row is
//     loaded AFTER the score (off the critical path, overlapping the next
//     step's W_in load) and FMA'd immediately with short live ranges to keep
//     regs <= 64 -> 8 blocks/SM.

#define DEPTH    11
#define NSTEPS   (DEPTH + 1)
#define N_NODES  4095
#define DDIM     2048
#define D4       (DDIM / 4)     // 512 float4 per row
#define BATCH    8192
#define THREADS  128

__device__ float g_WoutT[(size_t)N_NODES * DDIM];

// 64x64 tile transpose, 256 threads, 16 elems/thread, coalesced in and out.
__global__ __launch_bounds__(256) void transpose_wout(const float* __restrict__ Wout) {
    __shared__ float tile[64][65];
    const int n0 = blockIdx.x * 64;   // node dim (4095)
    const int o0 = blockIdx.y * 64;   // output dim (2048)
    const int tid = threadIdx.x;

    #pragma unroll
    for (int k = 0; k < 16; ++k) {
        int e = k * 256 + tid;
        int ol = e >> 6;
        int nl = e & 63;
        int n = n0 + nl;
        float v = 0.f;
        if (n < N_NODES)
            v = Wout[(size_t)(o0 + ol) * N_NODES + n];
        tile[nl][ol] = v;
    }
    __syncthreads();

    #pragma unroll
    for (int k = 0; k < 16; ++k) {
        int e = k * 256 + tid;
        int nl = e >> 6;
        int ol = e & 63;
        int n = n0 + nl;
        if (n < N_NODES)
            g_WoutT[(size_t)n * DDIM + (o0 + ol)] = tile[nl][ol];
    }
}

__device__ __forceinline__ float dot4(float4 a, float4 b) {
    return fmaf(a.x, b.x, fmaf(a.y, b.y, fmaf(a.z, b.z, a.w * b.w)));
}

__device__ __forceinline__ void fma4(float4& a, float g, float4 v) {
    a.x = fmaf(g, v.x, a.x);
    a.y = fmaf(g, v.y, a.y);
    a.z = fmaf(g, v.z, a.z);
    a.w = fmaf(g, v.w, a.w);
}

__global__ __launch_bounds__(THREADS, 8) void fff_kernel(
    const float* __restrict__ x,
    const float* __restrict__ Win,
    float*       __restrict__ out)
{
    const int b    = blockIdx.x;
    const int tid  = threadIdx.x;
    const int lane = tid & 31;
    const int warp = tid >> 5;

    const float4* __restrict__ x4   = reinterpret_cast<const float4*>(x) + (size_t)b * D4;
    const float4* __restrict__ Win4 = reinterpret_cast<const float4*>(Win);
    const float4* __restrict__ Wt4  = reinterpret_cast<const float4*>(g_WoutT);

    // Cache this sample's x row in registers (coalesced LDG.128).
    float4 xr0 = x4[tid];
    float4 xr1 = x4[tid + 128];
    float4 xr2 = x4[tid + 256];
    float4 xr3 = x4[tid + 384];

    float4 a0 = make_float4(0.f, 0.f, 0.f, 0.f);
    float4 a1 = make_float4(0.f, 0.f, 0.f, 0.f);
    float4 a2 = make_float4(0.f, 0.f, 0.f, 0.f);
    float4 a3 = make_float4(0.f, 0.f, 0.f, 0.f);

    __shared__ float red[2][4];

    int node = 0;
    #pragma unroll
    for (int d = 0; d < NSTEPS; ++d) {
        const float4* __restrict__ wr = Win4 + (size_t)node * D4;

        // Routing load: on the critical path.
        float4 w0 = wr[tid];
        float4 w1 = wr[tid + 128];
        float4 w2 = wr[tid + 256];
        float4 w3 = wr[tid + 384];

        float p = dot4(w0, xr0);
        p += dot4(w1, xr1);
        p += dot4(w2, xr2);
        p += dot4(w3, xr3);

        // Warp reduce (fixed order -> deterministic).
        #pragma unroll
        for (int off = 16; off > 0; off >>= 1)
            p += __shfl_down_sync(0xffffffffu, p, off);

        if (lane == 0) red[d & 1][warp] = p;
        __syncthreads();

        // Every thread recomputes the same fixed-order sum -> identical score.
        float score = (red[d & 1][0] + red[d & 1][1])
                    + (red[d & 1][2] + red[d & 1][3]);

        // Exact GELU: 0.5*s*(1+erf(s/sqrt(2)))
        float g = 0.5f * score * (1.0f + erff(score * 0.70710678118654752f));

        const float4* __restrict__ vr = Wt4 + (size_t)node * D4;
        node = node * 2 + 1 + (score >= 0.0f ? 1 : 0);

        // Output row: loaded after score, off critical path (overlaps next
        // step's W_in load). Short live ranges keep register count low.
        fma4(a0, g, vr[tid]);
        fma4(a1, g, vr[tid + 128]);
        fma4(a2, g, vr[tid + 256]);
        fma4(a3, g, vr[tid + 384]);
    }

    float4* __restrict__ o4 = reinterpret_cast<float4*>(out) + (size_t)b * D4;
    o4[tid]       = a0;
    o4[tid + 128] = a1;
    o4[tid + 256] = a2;
    o4[tid + 384] = a3;
}

extern "C" void kernel_launch(void* const* d_in, const int* in_sizes, int n_in,
                              void* d_out, int out_size)
{
    const float* x    = (const float*)d_in[0];   // (8192, 2048)
    const float* Win  = (const float*)d_in[1];   // (4095, 2048)
    const float* Wout = (const float*)d_in[2];   // (2048, 4095)
    float* out = (float*)d_out;                  // (8192, 2048)

    dim3 tg((N_NODES + 63) / 64, DDIM / 64);     // 64 x 32 tiles
    transpose_wout<<<tg, 256>>>(Wout);

    fff_kernel<<<BATCH, THREADS>>>(x, Win, out);
}

// round 7
// speedup vs baseline: 1.2509x; 1.0200x over previous
#include <cuda_runtime.h>
#include <math.h>

// FFF: fast-feedforward conditional tree MLP.
// B=8192, D_in=D_out=2048, depth 11 -> 12 routing steps, 4095 nodes.
//
// k1 transpose_wout: W_out (2048 x 4095) -> g_WoutT (4095 x 2048).
// k2 route_kernel:   serial tree walk per sample, W_in traffic only.
//                    Emits (node, gelu(score)) x 12 per sample to scratch.
// k3 out_kernel:     out[b] = sum_d g_d * W_outT[node_d]. No serial chain;
//                    12 independent row gathers, fully unrolled -> runs at
//                    L1 bandwidth.

#define DEPTH    11
#define NSTEPS   (DEPTH + 1)
#define N_NODES  4095
#define DDIM     2048
#define D4       (DDIM / 4)     // 512 float4 per row
#define BATCH    8192
#define THREADS  128

__device__ float g_WoutT[(size_t)N_NODES * DDIM];
__device__ int   g_nodes[(size_t)BATCH * NSTEPS];
__device__ float g_gval [(size_t)BATCH * NSTEPS];

// 64x64 tile transpose, 256 threads, coalesced both sides.
__global__ __launch_bounds__(256) void transpose_wout(const float* __restrict__ Wout) {
    __shared__ float tile[64][65];
    const int n0 = blockIdx.x * 64;   // node dim (4095)
    const int o0 = blockIdx.y * 64;   // output dim (2048)
    const int tid = threadIdx.x;

    #pragma unroll
    for (int k = 0; k < 16; ++k) {
        int e = k * 256 + tid;
        int ol = e >> 6;
        int nl = e & 63;
        int n = n0 + nl;
        float v = 0.f;
        if (n < N_NODES)
            v = Wout[(size_t)(o0 + ol) * N_NODES + n];
        tile[nl][ol] = v;
    }
    __syncthreads();

    #pragma unroll
    for (int k = 0; k < 16; ++k) {
        int e = k * 256 + tid;
        int nl = e >> 6;
        int ol = e & 63;
        int n = n0 + nl;
        if (n < N_NODES)
            g_WoutT[(size_t)n * DDIM + (o0 + ol)] = tile[nl][ol];
    }
}

__device__ __forceinline__ float dot4(float4 a, float4 b) {
    return fmaf(a.x, b.x, fmaf(a.y, b.y, fmaf(a.z, b.z, a.w * b.w)));
}

__device__ __forceinline__ void fma4(float4& a, float g, float4 v) {
    a.x = fmaf(g, v.x, a.x);
    a.y = fmaf(g, v.y, a.y);
    a.z = fmaf(g, v.z, a.z);
    a.w = fmaf(g, v.w, a.w);
}

// Serial routing: one 128-thread block per sample; W_in traffic only.
__global__ __launch_bounds__(THREADS, 10) void route_kernel(
    const float* __restrict__ x,
    const float* __restrict__ Win)
{
    const int b    = blockIdx.x;
    const int tid  = threadIdx.x;
    const int lane = tid & 31;
    const int warp = tid >> 5;

    const float4* __restrict__ x4   = reinterpret_cast<const float4*>(x) + (size_t)b * D4;
    const float4* __restrict__ Win4 = reinterpret_cast<const float4*>(Win);

    float4 xr0 = x4[tid];
    float4 xr1 = x4[tid + 128];
    float4 xr2 = x4[tid + 256];
    float4 xr3 = x4[tid + 384];

    __shared__ float red[2][4];

    int node = 0;
    #pragma unroll
    for (int d = 0; d < NSTEPS; ++d) {
        const float4* __restrict__ wr = Win4 + (size_t)node * D4;

        float4 w0 = wr[tid];
        float4 w1 = wr[tid + 128];
        float4 w2 = wr[tid + 256];
        float4 w3 = wr[tid + 384];

        float p = dot4(w0, xr0);
        p += dot4(w1, xr1);
        p += dot4(w2, xr2);
        p += dot4(w3, xr3);

        // Warp reduce (fixed order -> deterministic).
        #pragma unroll
        for (int off = 16; off > 0; off >>= 1)
            p += __shfl_down_sync(0xffffffffu, p, off);

        if (lane == 0) red[d & 1][warp] = p;
        __syncthreads();

        float score = (red[d & 1][0] + red[d & 1][1])
                    + (red[d & 1][2] + red[d & 1][3]);

        if (tid == 0) {
            // Exact GELU: 0.5*s*(1+erf(s/sqrt(2)))
            float g = 0.5f * score * (1.0f + erff(score * 0.70710678118654752f));
            g_nodes[(size_t)b * NSTEPS + d] = node;
            g_gval [(size_t)b * NSTEPS + d] = g;
        }

        node = node * 2 + 1 + (score >= 0.0f ? 1 : 0);
    }
}

// Output accumulation: fully parallel, 12 independent row gathers per sample.
__global__ __launch_bounds__(THREADS, 8) void out_kernel(
    float* __restrict__ out)
{
    const int b   = blockIdx.x;
    const int tid = threadIdx.x;

    const float4* __restrict__ Wt4 = reinterpret_cast<const float4*>(g_WoutT);

    int   nd[NSTEPS];
    float gg[NSTEPS];
    #pragma unroll
    for (int d = 0; d < NSTEPS; ++d) {
        nd[d] = g_nodes[(size_t)b * NSTEPS + d];
        gg[d] = g_gval [(size_t)b * NSTEPS + d];
    }

    float4 a0 = make_float4(0.f, 0.f, 0.f, 0.f);
    float4 a1 = make_float4(0.f, 0.f, 0.f, 0.f);
    float4 a2 = make_float4(0.f, 0.f, 0.f, 0.f);
    float4 a3 = make_float4(0.f, 0.f, 0.f, 0.f);

    #pragma unroll
    for (int d = 0; d < NSTEPS; ++d) {
        const float4* __restrict__ vr = Wt4 + (size_t)nd[d] * D4;
        float g = gg[d];
        fma4(a0, g, vr[tid]);
        fma4(a1, g, vr[tid + 128]);
        fma4(a2, g, vr[tid + 256]);
        fma4(a3, g, vr[tid + 384]);
    }

    float4* __restrict__ o4 = reinterpret_cast<float4*>(out) + (size_t)b * D4;
    o4[tid]       = a0;
    o4[tid + 128] = a1;
    o4[tid + 256] = a2;
    o4[tid + 384] = a3;
}

extern "C" void kernel_launch(void* const* d_in, const int* in_sizes, int n_in,
                              void* d_out, int out_size)
{
    const float* x    = (const float*)d_in[0];   // (8192, 2048)
    const float* Win  = (const float*)d_in[1];   // (4095, 2048)
    const float* Wout = (const float*)d_in[2];   // (2048, 4095)
    float* out = (float*)d_out;                  // (8192, 2048)

    dim3 tg((N_NODES + 63) / 64, DDIM / 64);     // 64 x 32 tiles
    transpose_wout<<<tg, 256>>>(Wout);

    route_kernel<<<BATCH, THREADS>>>(x, Win);
    out_kernel<<<BATCH, THREADS>>>(out);
}